// round 5
// baseline (speedup 1.0000x reference)
#include <cuda_runtime.h>
#include <cuda_fp16.h>
#include <math.h>

#define H2 2048
#define T_STEPS 2048
#define NG 8192            // 4*H2
#define LAYERS 4
#define JJ 14              // h-elements per CTA
#define ROWS 56            // 4*JJ gate rows per CTA
#define NCTA 147           // ceil(2048/14)
#define SCAN_THREADS 256
#define SCAN_SMEM (ROWS * H2 * 2)   // 229376 bytes of fp16 weights

// ---------------- scratch (static device globals; no allocation) ----------------
__device__ float  g_xw[(size_t)T_STEPS * NG];        // 67 MB: xw for current layer
__device__ __align__(16) __half g_hseq[(size_t)T_STEPS * H2]; // h sequence (fp16) of current layer
__device__ __align__(16) __half g_hbuf[2][H2];       // double-buffered h for the scan
__device__ float  g_hlast[H2];                       // fp32 h at t=T-1
__device__ unsigned g_bar_count = 0;
__device__ unsigned g_bar_gen   = 0;

// ---------------- helpers ----------------
static __device__ __forceinline__ float2 h2_to_f2(unsigned u) {
    __half2 h;
    *reinterpret_cast<unsigned*>(&h) = u;
    return __half22float2(h);
}
static __device__ __forceinline__ uint2 ldcg_v2(const uint2* p) {
    uint2 v;
    asm volatile("ld.global.cg.v2.u32 {%0,%1}, [%2];" : "=r"(v.x), "=r"(v.y) : "l"(p));
    return v;
}
static __device__ __forceinline__ float sigmoidf_fast(float x) {
    return 1.0f / (1.0f + __expf(-x));
}
static __device__ __forceinline__ float tanhf_fast(float x) {
    return 2.0f / (1.0f + __expf(-2.0f * x)) - 1.0f;
}

// grid barrier: count + generation, self-resetting (graph-replay safe). thread 0 only.
static __device__ __forceinline__ void bar_arrive_wait_t0(unsigned& my_gen, unsigned nct) {
    unsigned old = atomicAdd(&g_bar_count, 1);
    my_gen += 1;
    if (old == nct - 1) {
        atomicExch(&g_bar_count, 0);
        __threadfence();
        atomicAdd(&g_bar_gen, 1);
    } else {
        while ((int)(atomicAdd(&g_bar_gen, 0) - my_gen) < 0) { __nanosleep(64); }
    }
    __threadfence();
}

// ---------------- layer-0 xw: xw[t][r] = event[t]*w_ih0[r] + b_ih[r] + b_hh[r] ----------------
__global__ void xw0_kernel(const float* __restrict__ event, const float* __restrict__ w0,
                           const float* __restrict__ bih, const float* __restrict__ bhh) {
    int t = blockIdx.y;
    int c = (blockIdx.x * blockDim.x + threadIdx.x) * 4;
    float e = event[t];
    float4 w  = *(const float4*)(w0 + c);
    float4 bi = *(const float4*)(bih + c);
    float4 bh = *(const float4*)(bhh + c);
    float4 r;
    r.x = fmaf(e, w.x, bi.x + bh.x);
    r.y = fmaf(e, w.y, bi.y + bh.y);
    r.z = fmaf(e, w.z, bi.z + bh.z);
    r.w = fmaf(e, w.w, bi.w + bh.w);
    *(float4*)(g_xw + (size_t)t * NG + c) = r;
}

// ---------------- xw GEMM: g_xw[t][r] = sum_k g_hseq[t][k] * B[r][k] + bias[r] ----------------
#define BM 128
#define BN 128
#define BK 32
#define SPAD 4

__global__ __launch_bounds__(256, 2) void gemm_xw(const float* __restrict__ B,
                                                  const float* __restrict__ bih,
                                                  const float* __restrict__ bhh) {
    __shared__ float As[BK][BM + SPAD];
    __shared__ float Bs[BK][BN + SPAD];
    const int tid = threadIdx.x;
    const int tx = tid & 15;
    const int ty = tid >> 4;
    const int row0 = blockIdx.y * BM;   // t
    const int col0 = blockIdx.x * BN;   // r

    const int lr = tid >> 1;            // 0..127 (tile row for loads)
    const int lc = (tid & 1) * 16;      // 0 or 16 (k offset for loads)
    const __half* aptr = g_hseq + (size_t)(row0 + lr) * H2 + lc;
    const float*  bptr = B      + (size_t)(col0 + lr) * H2 + lc;

    float acc[8][8];
#pragma unroll
    for (int i = 0; i < 8; i++)
#pragma unroll
        for (int j = 0; j < 8; j++) acc[i][j] = 0.0f;

    for (int k0 = 0; k0 < H2; k0 += BK) {
        // issue global loads before the sync (overlaps previous tile's compute)
        uint4 a0 = *(const uint4*)(aptr + k0);
        uint4 a1 = *(const uint4*)(aptr + k0 + 8);
        float4 b0 = *(const float4*)(bptr + k0);
        float4 b1 = *(const float4*)(bptr + k0 + 4);
        float4 b2 = *(const float4*)(bptr + k0 + 8);
        float4 b3 = *(const float4*)(bptr + k0 + 12);
        __syncthreads();
        {
            unsigned aw[8] = {a0.x, a0.y, a0.z, a0.w, a1.x, a1.y, a1.z, a1.w};
#pragma unroll
            for (int e = 0; e < 8; e++) {
                float2 f = h2_to_f2(aw[e]);
                As[lc + 2 * e][lr]     = f.x;
                As[lc + 2 * e + 1][lr] = f.y;
            }
            float bw[16] = {b0.x, b0.y, b0.z, b0.w, b1.x, b1.y, b1.z, b1.w,
                            b2.x, b2.y, b2.z, b2.w, b3.x, b3.y, b3.z, b3.w};
#pragma unroll
            for (int e = 0; e < 16; e++) Bs[lc + e][lr] = bw[e];
        }
        __syncthreads();
#pragma unroll
        for (int k = 0; k < BK; k++) {
            float4 xa = *(const float4*)&As[k][ty * 8];
            float4 xb = *(const float4*)&As[k][ty * 8 + 4];
            float4 ya = *(const float4*)&Bs[k][tx * 8];
            float4 yb = *(const float4*)&Bs[k][tx * 8 + 4];
            float av[8] = {xa.x, xa.y, xa.z, xa.w, xb.x, xb.y, xb.z, xb.w};
            float bv[8] = {ya.x, ya.y, ya.z, ya.w, yb.x, yb.y, yb.z, yb.w};
#pragma unroll
            for (int i = 0; i < 8; i++)
#pragma unroll
                for (int j = 0; j < 8; j++) acc[i][j] = fmaf(av[i], bv[j], acc[i][j]);
        }
    }

    float bias[8];
#pragma unroll
    for (int j = 0; j < 8; j++) {
        int c = col0 + tx * 8 + j;
        bias[j] = __ldg(bih + c) + __ldg(bhh + c);
    }
#pragma unroll
    for (int i = 0; i < 8; i++) {
        float* crow = g_xw + (size_t)(row0 + ty * 8 + i) * NG + col0 + tx * 8;
        float4 v0 = {acc[i][0] + bias[0], acc[i][1] + bias[1], acc[i][2] + bias[2], acc[i][3] + bias[3]};
        float4 v1 = {acc[i][4] + bias[4], acc[i][5] + bias[5], acc[i][6] + bias[6], acc[i][7] + bias[7]};
        *(float4*)crow = v0;
        *(float4*)(crow + 4) = v1;
    }
}

// ---------------- persistent LSTM scan ----------------
// CTA k owns h-elements j in [k*JJ, k*JJ+nj). SMEM holds its 56 W_hh rows in fp16.
// Per step: matvec (SMEM weights x fp16 h from L2, fp32 accum) -> warp reduce ->
// CTA-local gate combine -> publish h (fp16, double-buffered) -> grid barrier.
__global__ __launch_bounds__(SCAN_THREADS, 1) void lstm_scan(const float* __restrict__ whh,
                                                             int last_layer) {
    extern __shared__ __align__(16) unsigned char smem_raw[];
    __half2* wsh = (__half2*)smem_raw;          // ROWS x 1024 half2
    __shared__ float gpart[ROWS];
    __shared__ float cst[JJ];

    const int tid  = threadIdx.x;
    const int lane = tid & 31;
    const int warp = tid >> 5;
    const int j0   = blockIdx.x * JJ;
    const int nj   = (H2 - j0 < JJ) ? (H2 - j0) : JJ;

    unsigned my_gen = 0;
    if (tid == 0) my_gen = atomicAdd(&g_bar_gen, 0);

    // load + convert this CTA's 56 weight rows into SMEM (row r = gate*JJ + jl)
    for (int r = warp; r < ROWS; r += 8) {
        int gate = r / JJ;
        int jl = r - gate * JJ;
        __half2* dst = wsh + r * (H2 / 2);
        if (jl < nj) {
            const float2* src = (const float2*)(whh + ((size_t)gate * H2 + j0 + jl) * H2);
            for (int p = lane; p < H2 / 2; p += 32) {
                float2 v = __ldg(src + p);
                dst[p] = __floats2half2_rn(v.x, v.y);
            }
        } else {
            for (int p = lane; p < H2 / 2; p += 32) dst[p] = __half2half2(__float2half(0.0f));
        }
    }
    if (tid < JJ) cst[tid] = 0.0f;
    __syncthreads();

    for (int t = 0; t < T_STEPS; ++t) {
        // prefetch xw for this CTA's gate entries (combine uses them later)
        float xwi = 0.f, xwf = 0.f, xwg = 0.f, xwo = 0.f;
        if (tid < nj) {
            const float* xwt = g_xw + (size_t)t * NG + j0 + tid;
            xwi = __ldg(xwt);
            xwf = __ldg(xwt + H2);
            xwg = __ldg(xwt + 2 * H2);
            xwo = __ldg(xwt + 3 * H2);
        }

        // load h_{t-1} (fp16, L2-coherent via .cg) into registers: 64 floats per lane
        const uint2* hb = (const uint2*)(&g_hbuf[t & 1][0]);
        float hreg[64];
#pragma unroll
        for (int q = 0; q < 16; q++) {
            uint2 hv = ldcg_v2(hb + lane + 32 * q);
            float2 fa = h2_to_f2(hv.x);
            float2 fb = h2_to_f2(hv.y);
            hreg[4 * q]     = fa.x;
            hreg[4 * q + 1] = fa.y;
            hreg[4 * q + 2] = fb.x;
            hreg[4 * q + 3] = fb.y;
        }

        // 7 dot-product rows per warp
#pragma unroll
        for (int rr = 0; rr < 7; rr++) {
            int r = warp * 7 + rr;
            const uint2* wr = (const uint2*)(smem_raw + (size_t)r * H2 * 2);
            float a0 = 0.f, a1 = 0.f, a2 = 0.f, a3 = 0.f;
#pragma unroll
            for (int q = 0; q < 16; q++) {
                uint2 wv = wr[lane + 32 * q];
                float2 fa = h2_to_f2(wv.x);
                float2 fb = h2_to_f2(wv.y);
                a0 = fmaf(fa.x, hreg[4 * q],     a0);
                a1 = fmaf(fa.y, hreg[4 * q + 1], a1);
                a2 = fmaf(fb.x, hreg[4 * q + 2], a2);
                a3 = fmaf(fb.y, hreg[4 * q + 3], a3);
            }
            float a = (a0 + a1) + (a2 + a3);
#pragma unroll
            for (int o = 16; o; o >>= 1) a += __shfl_xor_sync(0xffffffffu, a, o);
            if (lane == 0) gpart[r] = a;
        }
        __syncthreads();

        // gate combine for this CTA's h-elements
        if (tid < nj) {
            int jl = tid;
            float gi = gpart[0 * JJ + jl] + xwi;
            float gf = gpart[1 * JJ + jl] + xwf;
            float gg = gpart[2 * JJ + jl] + xwg;
            float go = gpart[3 * JJ + jl] + xwo;
            float c = sigmoidf_fast(gf) * cst[jl] + sigmoidf_fast(gi) * tanhf_fast(gg);
            float h = sigmoidf_fast(go) * tanhf_fast(c);
            cst[jl] = c;
            int j = j0 + jl;
            __half hh = __float2half_rn(h);
            g_hbuf[(t + 1) & 1][j] = hh;                 // for next step's matvec
            g_hseq[(size_t)t * H2 + j] = hh;             // for next layer's GEMM
            if (last_layer && t == T_STEPS - 1) g_hlast[j] = h;
        }

        __threadfence();
        __syncthreads();
        if (tid == 0) bar_arrive_wait_t0(my_gen, gridDim.x);
        __syncthreads();
    }
}

// ---------------- final projection + log_softmax ----------------
__global__ void final_kernel(const float* __restrict__ wout, const float* __restrict__ bout,
                             float* __restrict__ out) {
    int tid = threadIdx.x;
    float s0 = 0.f, s1 = 0.f;
    for (int k = tid; k < H2; k += 256) {
        float h = g_hlast[k];
        s0 = fmaf(h, wout[k], s0);
        s1 = fmaf(h, wout[H2 + k], s1);
    }
    __shared__ float r0[8], r1[8];
#pragma unroll
    for (int o = 16; o; o >>= 1) {
        s0 += __shfl_xor_sync(0xffffffffu, s0, o);
        s1 += __shfl_xor_sync(0xffffffffu, s1, o);
    }
    if ((tid & 31) == 0) { r0[tid >> 5] = s0; r1[tid >> 5] = s1; }
    __syncthreads();
    if (tid == 0) {
        float l0 = bout[0], l1 = bout[1];
        for (int w = 0; w < 8; w++) { l0 += r0[w]; l1 += r1[w]; }
        float m = fmaxf(l0, l1);
        float z = expf(l0 - m) + expf(l1 - m);
        float lse = m + logf(z);
        out[0] = l0 - lse;
        out[1] = l1 - lse;
    }
}

// ---------------- launcher ----------------
extern "C" void kernel_launch(void* const* d_in, const int* in_sizes, int n_in,
                              void* d_out, int out_size) {
    const float* event = (const float*)d_in[0];
    const float* w_ih0 = (const float*)d_in[1];   // (8192, 1)
    const float* w_ih  = (const float*)d_in[2];   // (3, 8192, 2048)
    const float* w_hh  = (const float*)d_in[3];   // (4, 8192, 2048)
    const float* b_ih  = (const float*)d_in[4];   // (4, 8192)
    const float* b_hh  = (const float*)d_in[5];   // (4, 8192)
    const float* w_out = (const float*)d_in[6];   // (2, 2048)
    const float* b_out = (const float*)d_in[7];   // (2,)
    float* out = (float*)d_out;

    cudaFuncSetAttribute(lstm_scan, cudaFuncAttributeMaxDynamicSharedMemorySize, SCAN_SMEM);

    void* hbuf_ptr = nullptr;
    cudaGetSymbolAddress(&hbuf_ptr, g_hbuf);

    for (int l = 0; l < LAYERS; ++l) {
        if (l == 0) {
            dim3 grid(NG / (256 * 4), T_STEPS);
            xw0_kernel<<<grid, 256>>>(event, w_ih0, b_ih, b_hh);
        } else {
            dim3 grid(NG / BN, T_STEPS / BM);
            gemm_xw<<<grid, 256>>>(w_ih + (size_t)(l - 1) * NG * H2,
                                   b_ih + (size_t)l * NG,
                                   b_hh + (size_t)l * NG);
        }
        cudaMemsetAsync(hbuf_ptr, 0, 2 * H2 * sizeof(__half));
        lstm_scan<<<NCTA, SCAN_THREADS, SCAN_SMEM>>>(w_hh + (size_t)l * NG * H2,
                                                     (l == LAYERS - 1) ? 1 : 0);
    }
    final_kernel<<<1, 256>>>(w_out, b_out, out);
}

// round 6
// speedup vs baseline: 1.1275x; 1.1275x over previous
#include <cuda_runtime.h>
#include <cuda_fp16.h>
#include <math.h>

#define H2 2048
#define T_STEPS 2048
#define NG 8192            // 4*H2
#define LAYERS 4
#define JJ 14              // h-elements per CTA
#define ROWS 56            // 4*JJ gate rows per CTA
#define NCTA 147           // ceil(2048/14)
#define SCAN_THREADS 512
#define SCAN_SMEM (ROWS * H2 * 2)   // 229376 bytes of fp16 weights

// ---------------- scratch (static device globals; no allocation) ----------------
__device__ float  g_xw[(size_t)T_STEPS * NG];        // 67 MB: xw for current layer
__device__ __align__(16) __half g_hseq[(size_t)T_STEPS * H2]; // h sequence (fp16) of current layer
__device__ __align__(16) __half g_hbuf[2][H2];       // double-buffered h for the scan
__device__ float  g_hlast[H2];                       // fp32 h at t=T-1
__device__ unsigned g_bar_count = 0;
__device__ unsigned g_bar_gen   = 0;

// ---------------- helpers ----------------
static __device__ __forceinline__ float2 h2_to_f2(unsigned u) {
    __half2 h;
    *reinterpret_cast<unsigned*>(&h) = u;
    return __half22float2(h);
}
static __device__ __forceinline__ __half2 u2h2(unsigned u) {
    __half2 h;
    *reinterpret_cast<unsigned*>(&h) = u;
    return h;
}
static __device__ __forceinline__ uint4 ldcg_v4(const uint4* p) {
    uint4 v;
    asm volatile("ld.global.cg.v4.u32 {%0,%1,%2,%3}, [%4];"
                 : "=r"(v.x), "=r"(v.y), "=r"(v.z), "=r"(v.w) : "l"(p));
    return v;
}
static __device__ __forceinline__ float sigmoidf_fast(float x) {
    return 1.0f / (1.0f + __expf(-x));
}
static __device__ __forceinline__ float tanhf_fast(float x) {
    return 2.0f / (1.0f + __expf(-2.0f * x)) - 1.0f;
}

// grid barrier: count + generation, self-resetting (graph-replay safe). thread 0 only.
static __device__ __forceinline__ void bar_arrive_wait_t0(unsigned& my_gen, unsigned nct) {
    unsigned old = atomicAdd(&g_bar_count, 1);
    my_gen += 1;
    if (old == nct - 1) {
        atomicExch(&g_bar_count, 0);
        __threadfence();
        atomicAdd(&g_bar_gen, 1);
    } else {
        if ((int)(atomicAdd(&g_bar_gen, 0) - my_gen) < 0) {
            while ((int)(atomicAdd(&g_bar_gen, 0) - my_gen) < 0) { __nanosleep(32); }
        }
    }
    __threadfence();
}

// ---------------- layer-0 xw: xw[t][r] = event[t]*w_ih0[r] + b_ih[r] + b_hh[r] ----------------
__global__ void xw0_kernel(const float* __restrict__ event, const float* __restrict__ w0,
                           const float* __restrict__ bih, const float* __restrict__ bhh) {
    int t = blockIdx.y;
    int c = (blockIdx.x * blockDim.x + threadIdx.x) * 4;
    float e = event[t];
    float4 w  = *(const float4*)(w0 + c);
    float4 bi = *(const float4*)(bih + c);
    float4 bh = *(const float4*)(bhh + c);
    float4 r;
    r.x = fmaf(e, w.x, bi.x + bh.x);
    r.y = fmaf(e, w.y, bi.y + bh.y);
    r.z = fmaf(e, w.z, bi.z + bh.z);
    r.w = fmaf(e, w.w, bi.w + bh.w);
    *(float4*)(g_xw + (size_t)t * NG + c) = r;
}

// ---------------- xw GEMM: g_xw[t][r] = sum_k g_hseq[t][k] * B[r][k] + bias[r] ----------------
#define BM 128
#define BN 128
#define BK 32
#define SPAD 4

__global__ __launch_bounds__(256, 2) void gemm_xw(const float* __restrict__ B,
                                                  const float* __restrict__ bih,
                                                  const float* __restrict__ bhh) {
    __shared__ float As[BK][BM + SPAD];
    __shared__ float Bs[BK][BN + SPAD];
    const int tid = threadIdx.x;
    const int tx = tid & 15;
    const int ty = tid >> 4;
    const int row0 = blockIdx.y * BM;   // t
    const int col0 = blockIdx.x * BN;   // r

    const int lr = tid >> 1;            // 0..127 (tile row for loads)
    const int lc = (tid & 1) * 16;      // 0 or 16 (k offset for loads)
    const __half* aptr = g_hseq + (size_t)(row0 + lr) * H2 + lc;
    const float*  bptr = B      + (size_t)(col0 + lr) * H2 + lc;

    float acc[8][8];
#pragma unroll
    for (int i = 0; i < 8; i++)
#pragma unroll
        for (int j = 0; j < 8; j++) acc[i][j] = 0.0f;

    for (int k0 = 0; k0 < H2; k0 += BK) {
        uint4 a0 = *(const uint4*)(aptr + k0);
        uint4 a1 = *(const uint4*)(aptr + k0 + 8);
        float4 b0 = *(const float4*)(bptr + k0);
        float4 b1 = *(const float4*)(bptr + k0 + 4);
        float4 b2 = *(const float4*)(bptr + k0 + 8);
        float4 b3 = *(const float4*)(bptr + k0 + 12);
        __syncthreads();
        {
            unsigned aw[8] = {a0.x, a0.y, a0.z, a0.w, a1.x, a1.y, a1.z, a1.w};
#pragma unroll
            for (int e = 0; e < 8; e++) {
                float2 f = h2_to_f2(aw[e]);
                As[lc + 2 * e][lr]     = f.x;
                As[lc + 2 * e + 1][lr] = f.y;
            }
            float bw[16] = {b0.x, b0.y, b0.z, b0.w, b1.x, b1.y, b1.z, b1.w,
                            b2.x, b2.y, b2.z, b2.w, b3.x, b3.y, b3.z, b3.w};
#pragma unroll
            for (int e = 0; e < 16; e++) Bs[lc + e][lr] = bw[e];
        }
        __syncthreads();
#pragma unroll
        for (int k = 0; k < BK; k++) {
            float4 xa = *(const float4*)&As[k][ty * 8];
            float4 xb = *(const float4*)&As[k][ty * 8 + 4];
            float4 ya = *(const float4*)&Bs[k][tx * 8];
            float4 yb = *(const float4*)&Bs[k][tx * 8 + 4];
            float av[8] = {xa.x, xa.y, xa.z, xa.w, xb.x, xb.y, xb.z, xb.w};
            float bv[8] = {ya.x, ya.y, ya.z, ya.w, yb.x, yb.y, yb.z, yb.w};
#pragma unroll
            for (int i = 0; i < 8; i++)
#pragma unroll
                for (int j = 0; j < 8; j++) acc[i][j] = fmaf(av[i], bv[j], acc[i][j]);
        }
    }

    float bias[8];
#pragma unroll
    for (int j = 0; j < 8; j++) {
        int c = col0 + tx * 8 + j;
        bias[j] = __ldg(bih + c) + __ldg(bhh + c);
    }
#pragma unroll
    for (int i = 0; i < 8; i++) {
        float* crow = g_xw + (size_t)(row0 + ty * 8 + i) * NG + col0 + tx * 8;
        float4 v0 = {acc[i][0] + bias[0], acc[i][1] + bias[1], acc[i][2] + bias[2], acc[i][3] + bias[3]};
        float4 v1 = {acc[i][4] + bias[4], acc[i][5] + bias[5], acc[i][6] + bias[6], acc[i][7] + bias[7]};
        *(float4*)crow = v0;
        *(float4*)(crow + 4) = v1;
    }
}

// ---------------- persistent LSTM scan (v2: 512 thr, K-split, HFMA2) ----------------
// CTA k owns h-elements j in [k*JJ, k*JJ+nj). SMEM holds its 56 W_hh rows in fp16.
// 16 warps: warp = grp + 8*khalf. Warp pair (grp,0)/(grp,1) handles rows
// [7*grp, 7*grp+7), each over half of K. Accumulation: 4 half2 accumulators
// (4 products each), promoted to fp32 before the warp shuffle reduce.
__global__ __launch_bounds__(SCAN_THREADS, 1) void lstm_scan(const float* __restrict__ whh,
                                                             int last_layer) {
    extern __shared__ __align__(16) unsigned char smem_raw[];
    __half2* wsh = (__half2*)smem_raw;          // ROWS x 1024 half2
    __shared__ float gpart[2][ROWS];
    __shared__ float cst[JJ];

    const int tid  = threadIdx.x;
    const int lane = tid & 31;
    const int warp = tid >> 5;
    const int grp  = warp & 7;
    const int khalf = warp >> 3;
    const int koff = khalf * 128;               // uint4 offset into a row (256 uint4/row)
    const int j0   = blockIdx.x * JJ;
    const int nj   = (H2 - j0 < JJ) ? (H2 - j0) : JJ;

    unsigned my_gen = 0;
    if (tid == 0) my_gen = atomicAdd(&g_bar_gen, 0);

    // load + convert this CTA's 56 weight rows into SMEM (row r = gate*JJ + jl)
    for (int r = warp; r < ROWS; r += 16) {
        int gate = r / JJ;
        int jl = r - gate * JJ;
        __half2* dst = wsh + r * (H2 / 2);
        if (jl < nj) {
            const float2* src = (const float2*)(whh + ((size_t)gate * H2 + j0 + jl) * H2);
            for (int p = lane; p < H2 / 2; p += 32) {
                float2 v = __ldg(src + p);
                dst[p] = __floats2half2_rn(v.x, v.y);
            }
        } else {
            for (int p = lane; p < H2 / 2; p += 32) dst[p] = __half2half2(__float2half(0.0f));
        }
    }
    if (tid < JJ) cst[tid] = 0.0f;
    __syncthreads();

    const uint4* wbase = (const uint4*)smem_raw;

    for (int t = 0; t < T_STEPS; ++t) {
        // prefetch xw for this CTA's gate entries (combine uses them later)
        float xwi = 0.f, xwf = 0.f, xwg = 0.f, xwo = 0.f;
        if (tid < nj) {
            const float* xwt = g_xw + (size_t)t * NG + j0 + tid;
            xwi = __ldg(xwt);
            xwf = __ldg(xwt + H2);
            xwg = __ldg(xwt + 2 * H2);
            xwo = __ldg(xwt + 3 * H2);
        }

        // load this warp's K-half of h_{t-1} (fp16, L2-coherent .cg): 16 half2 regs
        const uint4* hb = ((const uint4*)(&g_hbuf[t & 1][0])) + koff;
        uint4 hu0 = ldcg_v4(hb + lane);
        uint4 hu1 = ldcg_v4(hb + lane + 32);
        uint4 hu2 = ldcg_v4(hb + lane + 64);
        uint4 hu3 = ldcg_v4(hb + lane + 96);
        __half2 hh[16];
        hh[0]=u2h2(hu0.x); hh[1]=u2h2(hu0.y); hh[2]=u2h2(hu0.z); hh[3]=u2h2(hu0.w);
        hh[4]=u2h2(hu1.x); hh[5]=u2h2(hu1.y); hh[6]=u2h2(hu1.z); hh[7]=u2h2(hu1.w);
        hh[8]=u2h2(hu2.x); hh[9]=u2h2(hu2.y); hh[10]=u2h2(hu2.z); hh[11]=u2h2(hu2.w);
        hh[12]=u2h2(hu3.x); hh[13]=u2h2(hu3.y); hh[14]=u2h2(hu3.z); hh[15]=u2h2(hu3.w);

        // 7 dot-product rows per warp, over this warp's K-half
#pragma unroll
        for (int rr = 0; rr < 7; rr++) {
            int r = grp * 7 + rr;
            const uint4* wr = wbase + (size_t)r * 256 + koff;
            uint4 wv0 = wr[lane];
            uint4 wv1 = wr[lane + 32];
            uint4 wv2 = wr[lane + 64];
            uint4 wv3 = wr[lane + 96];
            __half2 zero = __half2half2(__float2half(0.0f));
            __half2 a0 = zero, a1 = zero, a2 = zero, a3 = zero;
            a0 = __hfma2(u2h2(wv0.x), hh[0],  a0);
            a1 = __hfma2(u2h2(wv0.y), hh[1],  a1);
            a2 = __hfma2(u2h2(wv0.z), hh[2],  a2);
            a3 = __hfma2(u2h2(wv0.w), hh[3],  a3);
            a0 = __hfma2(u2h2(wv1.x), hh[4],  a0);
            a1 = __hfma2(u2h2(wv1.y), hh[5],  a1);
            a2 = __hfma2(u2h2(wv1.z), hh[6],  a2);
            a3 = __hfma2(u2h2(wv1.w), hh[7],  a3);
            a0 = __hfma2(u2h2(wv2.x), hh[8],  a0);
            a1 = __hfma2(u2h2(wv2.y), hh[9],  a1);
            a2 = __hfma2(u2h2(wv2.z), hh[10], a2);
            a3 = __hfma2(u2h2(wv2.w), hh[11], a3);
            a0 = __hfma2(u2h2(wv3.x), hh[12], a0);
            a1 = __hfma2(u2h2(wv3.y), hh[13], a1);
            a2 = __hfma2(u2h2(wv3.z), hh[14], a2);
            a3 = __hfma2(u2h2(wv3.w), hh[15], a3);
            float2 f0 = __half22float2(a0);
            float2 f1 = __half22float2(a1);
            float2 f2 = __half22float2(a2);
            float2 f3 = __half22float2(a3);
            float a = ((f0.x + f0.y) + (f1.x + f1.y)) + ((f2.x + f2.y) + (f3.x + f3.y));
#pragma unroll
            for (int o = 16; o; o >>= 1) a += __shfl_xor_sync(0xffffffffu, a, o);
            if (lane == 0) gpart[khalf][r] = a;
        }
        __syncthreads();

        // gate combine + publish (warp 0 only), then grid barrier by thread 0
        if (warp == 0) {
            if (lane < nj) {
                int jl = lane;
                float gi = gpart[0][0 * JJ + jl] + gpart[1][0 * JJ + jl] + xwi;
                float gf = gpart[0][1 * JJ + jl] + gpart[1][1 * JJ + jl] + xwf;
                float gg = gpart[0][2 * JJ + jl] + gpart[1][2 * JJ + jl] + xwg;
                float go = gpart[0][3 * JJ + jl] + gpart[1][3 * JJ + jl] + xwo;
                float c = sigmoidf_fast(gf) * cst[jl] + sigmoidf_fast(gi) * tanhf_fast(gg);
                float h = sigmoidf_fast(go) * tanhf_fast(c);
                cst[jl] = c;
                int j = j0 + jl;
                __half hhv = __float2half_rn(h);
                g_hbuf[(t + 1) & 1][j] = hhv;                 // for next step's matvec
                g_hseq[(size_t)t * H2 + j] = hhv;             // for next layer's GEMM
                if (last_layer && t == T_STEPS - 1) g_hlast[j] = h;
            }
            __syncwarp();
            if (lane == 0) {
                __threadfence();
                bar_arrive_wait_t0(my_gen, gridDim.x);
            }
        }
        __syncthreads();
    }
}

// ---------------- final projection + log_softmax ----------------
__global__ void final_kernel(const float* __restrict__ wout, const float* __restrict__ bout,
                             float* __restrict__ out) {
    int tid = threadIdx.x;
    float s0 = 0.f, s1 = 0.f;
    for (int k = tid; k < H2; k += 256) {
        float h = g_hlast[k];
        s0 = fmaf(h, wout[k], s0);
        s1 = fmaf(h, wout[H2 + k], s1);
    }
    __shared__ float r0[8], r1[8];
#pragma unroll
    for (int o = 16; o; o >>= 1) {
        s0 += __shfl_xor_sync(0xffffffffu, s0, o);
        s1 += __shfl_xor_sync(0xffffffffu, s1, o);
    }
    if ((tid & 31) == 0) { r0[tid >> 5] = s0; r1[tid >> 5] = s1; }
    __syncthreads();
    if (tid == 0) {
        float l0 = bout[0], l1 = bout[1];
        for (int w = 0; w < 8; w++) { l0 += r0[w]; l1 += r1[w]; }
        float m = fmaxf(l0, l1);
        float z = expf(l0 - m) + expf(l1 - m);
        float lse = m + logf(z);
        out[0] = l0 - lse;
        out[1] = l1 - lse;
    }
}

// ---------------- launcher ----------------
extern "C" void kernel_launch(void* const* d_in, const int* in_sizes, int n_in,
                              void* d_out, int out_size) {
    const float* event = (const float*)d_in[0];
    const float* w_ih0 = (const float*)d_in[1];   // (8192, 1)
    const float* w_ih  = (const float*)d_in[2];   // (3, 8192, 2048)
    const float* w_hh  = (const float*)d_in[3];   // (4, 8192, 2048)
    const float* b_ih  = (const float*)d_in[4];   // (4, 8192)
    const float* b_hh  = (const float*)d_in[5];   // (4, 8192)
    const float* w_out = (const float*)d_in[6];   // (2, 2048)
    const float* b_out = (const float*)d_in[7];   // (2,)
    float* out = (float*)d_out;

    cudaFuncSetAttribute(lstm_scan, cudaFuncAttributeMaxDynamicSharedMemorySize, SCAN_SMEM);

    void* hbuf_ptr = nullptr;
    cudaGetSymbolAddress(&hbuf_ptr, g_hbuf);

    for (int l = 0; l < LAYERS; ++l) {
        if (l == 0) {
            dim3 grid(NG / (256 * 4), T_STEPS);
            xw0_kernel<<<grid, 256>>>(event, w_ih0, b_ih, b_hh);
        } else {
            dim3 grid(NG / BN, T_STEPS / BM);
            gemm_xw<<<grid, 256>>>(w_ih + (size_t)(l - 1) * NG * H2,
                                   b_ih + (size_t)l * NG,
                                   b_hh + (size_t)l * NG);
        }
        cudaMemsetAsync(hbuf_ptr, 0, 2 * H2 * sizeof(__half));
        lstm_scan<<<NCTA, SCAN_THREADS, SCAN_SMEM>>>(w_hh + (size_t)l * NG * H2,
                                                     (l == LAYERS - 1) ? 1 : 0);
    }
    final_kernel<<<1, 256>>>(w_out, b_out, out);
}